// round 13
// baseline (speedup 1.0000x reference)
#include <cuda_runtime.h>
#include <cuda_bf16.h>
#include <cuda_fp16.h>
#include <cstdint>
#include <cstddef>

#define NN_MAX 50000
#define NE_MAX 800000
#define F_HID  128
#define N_CLS  40
#define NCLS_PAD 64
#define ELLW   64

// ---------------------------------------------------------------------------
// PTX helpers (compute_100-safe: ldmatrix + mma.sync only)
// ---------------------------------------------------------------------------
__device__ __forceinline__ uint32_t smem_to_u32(const void* p) {
    uint32_t a;
    asm("{ .reg .u64 t; cvta.to.shared.u64 t, %1; cvt.u32.u64 %0, t; }" : "=r"(a) : "l"(p));
    return a;
}
__device__ __forceinline__ void ldsm4(uint32_t* r, uint32_t addr) {
    asm volatile("ldmatrix.sync.aligned.m8n8.x4.shared.b16 {%0,%1,%2,%3}, [%4];"
                 : "=r"(r[0]), "=r"(r[1]), "=r"(r[2]), "=r"(r[3]) : "r"(addr));
}
__device__ __forceinline__ void mma16816(float* c, const uint32_t* a, const uint32_t* b) {
    asm volatile(
        "mma.sync.aligned.m16n8k16.row.col.f32.bf16.bf16.f32 "
        "{%0,%1,%2,%3}, {%4,%5,%6,%7}, {%8,%9}, {%0,%1,%2,%3};"
        : "+f"(c[0]), "+f"(c[1]), "+f"(c[2]), "+f"(c[3])
        : "r"(a[0]), "r"(a[1]), "r"(a[2]), "r"(a[3]), "r"(b[0]), "r"(b[1]));
}

// ---------------------------------------------------------------------------
// Scratch
// ---------------------------------------------------------------------------
__device__ __align__(16) __half g_H [(size_t)NN_MAX * F_HID];  // GEMM out (fp16, pre-agg)
__device__ __align__(16) __half g_h1[(size_t)NN_MAX * F_HID];  // layer-1 act (fp16)
__device__ __align__(16) __half g_jk[(size_t)NN_MAX * F_HID];  // JK-max (fp16)
__device__ __align__(16) __nv_bfloat16 g_w1h[F_HID * F_HID];
__device__ __align__(16) __nv_bfloat16 g_w1l[F_HID * F_HID];
__device__ __align__(16) __nv_bfloat16 g_wxh[F_HID * F_HID];
__device__ __align__(16) __nv_bfloat16 g_wxl[F_HID * F_HID];
__device__ __align__(16) __nv_bfloat16 g_wfh[NCLS_PAD * F_HID];
__device__ __align__(16) __nv_bfloat16 g_wfl[NCLS_PAD * F_HID];
__device__ int   g_deg [NN_MAX];                              // atomic cursors == degrees
__device__ float g_dinv[NN_MAX];
__device__ __align__(16) int   g_ells[(size_t)NN_MAX * ELLW]; // ELL: src ids
__device__ __align__(16) uint2 g_elle[(size_t)NN_MAX * ELLW]; // ELL: (src, dinv[src] bits)

// ---------------------------------------------------------------------------
// Graph preprocessing: single-pass ELL scatter (no count/scan), then dinv,
// then a coalesced fill pass packing (src, w) records for the agg loop.
// ---------------------------------------------------------------------------
__global__ void k_scatter(const int* __restrict__ ei, int ne) {
    int base = (blockIdx.x * blockDim.x + threadIdx.x) * 2;
    if (base + 1 < ne) {
        int2 s = *(const int2*)(ei + base);
        int2 d = *(const int2*)(ei + ne + base);
        int p0 = atomicAdd(&g_deg[d.x], 1);
        if (p0 < ELLW) g_ells[(size_t)d.x * ELLW + p0] = s.x;
        int p1 = atomicAdd(&g_deg[d.y], 1);
        if (p1 < ELLW) g_ells[(size_t)d.y * ELLW + p1] = s.y;
    } else {
        for (int k = base; k < ne; k++) {
            int s = ei[k], d = ei[ne + k];
            int p = atomicAdd(&g_deg[d], 1);
            if (p < ELLW) g_ells[(size_t)d * ELLW + p] = s;
        }
    }
}
__global__ void k_dinv(int nn) {
    int i = blockIdx.x * blockDim.x + threadIdx.x;
    if (i < nn) g_dinv[i] = rsqrtf((float)g_deg[i] + 1.0f);
}
// pack used ELL slots into (src, dinv[src]) uint2 records
__global__ void k_fill(int nn) {
    int idx = blockIdx.x * blockDim.x + threadIdx.x;
    if (idx >= nn * ELLW) return;
    int v = idx >> 6;
    int slot = idx & (ELLW - 1);
    int deg = g_deg[v];
    if (deg > ELLW) deg = ELLW;
    if (slot < deg) {
        int s = g_ells[idx];
        g_elle[idx] = make_uint2((uint32_t)s, __float_as_uint(g_dinv[s]));
    }
}

// ---------------------------------------------------------------------------
// bf16 hi/lo split
// ---------------------------------------------------------------------------
__device__ __forceinline__ void split_bf16(float v, __nv_bfloat16& hi, __nv_bfloat16& lo) {
    hi = __float2bfloat16(v);
    lo = __float2bfloat16(v - __bfloat162float(hi));
}

// All three weight matrices, transposed + split, one launch.
__global__ void k_wsplit_all(const float* __restrict__ W1, const float* __restrict__ Wx,
                             const float* __restrict__ Wfc) {
    int idx = blockIdx.x * 256 + threadIdx.x;
    const int S1 = F_HID * F_HID;          // 16384
    const int S2 = 2 * S1;                 // 32768
    const int S3 = S2 + NCLS_PAD * F_HID;  // 40960
    if (idx < S1) {
        int n = idx / F_HID, k = idx % F_HID;
        __nv_bfloat16 h, l;
        split_bf16(W1[k * F_HID + n], h, l);
        g_w1h[idx] = h;
        g_w1l[idx] = l;
    } else if (idx < S2) {
        int j = idx - S1;
        int n = j / F_HID, k = j % F_HID;
        __nv_bfloat16 h, l;
        split_bf16(Wx[k * F_HID + n], h, l);
        g_wxh[j] = h;
        g_wxl[j] = l;
    } else if (idx < S3) {
        int j = idx - S2;
        int n = j / F_HID, k = j % F_HID;
        float v = (n < N_CLS) ? Wfc[k * N_CLS + n] : 0.0f;
        __nv_bfloat16 h, l;
        split_bf16(v, h, l);
        g_wfh[j] = h;
        g_wfl[j] = l;
    }
}

// ---------------------------------------------------------------------------
// Aggregation: one WARP = one dst node, 32 lanes x 4 fp16 feats, fp32 FFMA.
// Inner loop byte-identical to R8/R12; rows come from the packed uint2 ELL.
// ---------------------------------------------------------------------------
__device__ __forceinline__ void unp4(uint2 p, float& x, float& y, float& z, float& w) {
    float2 f01 = __half22float2(*(__half2*)&p.x);
    float2 f23 = __half22float2(*(__half2*)&p.y);
    x = f01.x; y = f01.y; z = f23.x; w = f23.y;
}
__global__ void __launch_bounds__(256)
k_agg(const __half* __restrict__ H, const float* __restrict__ bias,
      const __half* __restrict__ m, __half* __restrict__ outp, int nn) {
    int wid = threadIdx.x >> 5;
    int lane = threadIdx.x & 31;
    int v = blockIdx.x * 8 + wid;
    if (v >= nn) return;

    const uint2* H2 = (const uint2*)H;
    float dv = g_dinv[v];
    float ax, ay, az, aw;
    unp4(H2[(size_t)v * 32 + lane], ax, ay, az, aw);
    ax *= dv; ay *= dv; az *= dv; aw *= dv;

    int deg = g_deg[v];
    if (deg > ELLW) deg = ELLW;
    const uint2* row = g_elle + (size_t)v * ELLW;
    int i = 0;
    for (; i + 4 <= deg; i += 4) {
        uint2 e0 = row[i + 0];
        uint2 e1 = row[i + 1];
        uint2 e2 = row[i + 2];
        uint2 e3 = row[i + 3];
        float w0 = __uint_as_float(e0.y), w1 = __uint_as_float(e1.y);
        float w2 = __uint_as_float(e2.y), w3 = __uint_as_float(e3.y);
        uint2 p0 = H2[(size_t)e0.x * 32 + lane];
        uint2 p1 = H2[(size_t)e1.x * 32 + lane];
        uint2 p2 = H2[(size_t)e2.x * 32 + lane];
        uint2 p3 = H2[(size_t)e3.x * 32 + lane];
        float x0, y0, z0, q0, x1, y1, z1, q1, x2, y2, z2, q2, x3, y3, z3, q3;
        unp4(p0, x0, y0, z0, q0);
        unp4(p1, x1, y1, z1, q1);
        unp4(p2, x2, y2, z2, q2);
        unp4(p3, x3, y3, z3, q3);
        ax += x0 * w0 + x1 * w1 + x2 * w2 + x3 * w3;
        ay += y0 * w0 + y1 * w1 + y2 * w2 + y3 * w3;
        az += z0 * w0 + z1 * w1 + z2 * w2 + z3 * w3;
        aw += q0 * w0 + q1 * w1 + q2 * w2 + q3 * w3;
    }
    for (; i < deg; i++) {
        uint2 ew = row[i];
        float w = __uint_as_float(ew.y);
        float x0, y0, z0, q0;
        unp4(H2[(size_t)ew.x * 32 + lane], x0, y0, z0, q0);
        ax += x0 * w;
        ay += y0 * w;
        az += z0 * w;
        aw += q0 * w;
    }

    float4 b = ((const float4*)bias)[lane];
    float rx = fmaxf(ax * dv + b.x, 0.0f);
    float ry = fmaxf(ay * dv + b.y, 0.0f);
    float rz = fmaxf(az * dv + b.z, 0.0f);
    float rw = fmaxf(aw * dv + b.w, 0.0f);
    if (m) {
        uint2 pm = ((const uint2*)m)[(size_t)v * 32 + lane];
        float mx, my, mz, mw;
        unp4(pm, mx, my, mz, mw);
        rx = fmaxf(rx, mx);
        ry = fmaxf(ry, my);
        rz = fmaxf(rz, mz);
        rw = fmaxf(rw, mw);
    }

    uint2 po;
    __half2 o01 = __floats2half2_rn(rx, ry);
    __half2 o23 = __floats2half2_rn(rz, rw);
    po.x = *(uint32_t*)&o01;
    po.y = *(uint32_t*)&o23;
    ((uint2*)outp)[(size_t)v * 32 + lane] = po;
}

// ---------------------------------------------------------------------------
// HMMA GEMM: C[M, NOUT] = (Ah+Al)[M,128] @ (Bh+Bl)^T
// B preformed [NT][128] bf16 hi/lo. AMODE: 0 = A fp32, 1 = A fp16 (both split
// into bf16 hi/lo in-kernel; fp16 split is exact). HOUT: fp16 out else fp32+bias.
// ---------------------------------------------------------------------------
template <int NT, int AMODE, bool HOUT>
__global__ void __launch_bounds__(256)
k_gemm(int M, const void* __restrict__ Av,
       const __nv_bfloat16* __restrict__ Bh, const __nv_bfloat16* __restrict__ Bl,
       const float* __restrict__ bias, int NOUT, void* __restrict__ Cv) {
    extern __shared__ __align__(16) char smem[];
    constexpr int ROWB = 272;
    constexpr int ABYTES = 128 * ROWB;
    constexpr int BBYTES = NT * ROWB;
    constexpr int NTILES = NT / 16;
    constexpr int NPAIR  = NT / 32;

    char* sAh = smem;
    char* sAl = smem + ABYTES;
    char* sBh = smem + 2 * ABYTES;
    char* sBl = smem + 2 * ABYTES + BBYTES;

    int tid = threadIdx.x;
    int block = blockIdx.x;

    if (AMODE == 0) {
        const float* Af = (const float*)Av;
#pragma unroll
        for (int it = 0; it < 16; ++it) {
            int idx = tid + it * 256;
            int r = idx >> 5, c4 = idx & 31;
            int grow = block * 128 + r;
            float4 v = make_float4(0.f, 0.f, 0.f, 0.f);
            if (grow < M) v = *(const float4*)(Af + (size_t)grow * 128 + c4 * 4);
            __nv_bfloat16 h0, l0, h1, l1, h2, l2, h3, l3;
            split_bf16(v.x, h0, l0);
            split_bf16(v.y, h1, l1);
            split_bf16(v.z, h2, l2);
            split_bf16(v.w, h3, l3);
            __nv_bfloat162 a01 = {h0, h1}, a23 = {h2, h3}, b01 = {l0, l1}, b23 = {l2, l3};
            uint2 ph, pl;
            ph.x = *(uint32_t*)&a01;
            ph.y = *(uint32_t*)&a23;
            pl.x = *(uint32_t*)&b01;
            pl.y = *(uint32_t*)&b23;
            *(uint2*)(sAh + r * ROWB + c4 * 8) = ph;
            *(uint2*)(sAl + r * ROWB + c4 * 8) = pl;
        }
    } else {
        const __half* Af = (const __half*)Av;
#pragma unroll
        for (int it = 0; it < 8; ++it) {
            int idx = tid + it * 256;            // 16B fp16 chunks (8 halves)
            int r = idx >> 4, c16 = idx & 15;
            int grow = block * 128 + r;
            uint4 v = make_uint4(0, 0, 0, 0);
            if (grow < M) v = *(const uint4*)(Af + (size_t)grow * 128 + c16 * 8);
            const __half2* hp = (const __half2*)&v;
            uint4 vh, vl;
            uint32_t* vhp = (uint32_t*)&vh;
            uint32_t* vlp = (uint32_t*)&vl;
#pragma unroll
            for (int j = 0; j < 4; j++) {
                float2 f = __half22float2(hp[j]);
                __nv_bfloat16 h0, l0, h1, l1;
                split_bf16(f.x, h0, l0);
                split_bf16(f.y, h1, l1);
                __nv_bfloat162 hh = {h0, h1}, ll = {l0, l1};
                vhp[j] = *(uint32_t*)&hh;
                vlp[j] = *(uint32_t*)&ll;
            }
            *(uint4*)(sAh + r * ROWB + c16 * 16) = vh;
            *(uint4*)(sAl + r * ROWB + c16 * 16) = vl;
        }
    }
    for (int idx = tid; idx < NT * 16; idx += 256) {
        int r = idx >> 4, c16 = idx & 15;
        *(uint4*)(sBh + r * ROWB + c16 * 16) = *(const uint4*)(Bh + (size_t)r * 128 + c16 * 8);
        *(uint4*)(sBl + r * ROWB + c16 * 16) = *(const uint4*)(Bl + (size_t)r * 128 + c16 * 8);
    }
    __syncthreads();

    int wid = tid >> 5, lane = tid & 31;
    int wm = wid & 3, wn = wid >> 2;
    int r0 = wm * 32;
    int n0 = wn * (NT / 2);

    uint32_t aoff = (uint32_t)(r0 + (lane & 15)) * ROWB + ((lane >> 4) * 16);
    uint32_t aAh0 = smem_to_u32(sAh) + aoff;
    uint32_t aAh1 = aAh0 + 16 * ROWB;
    uint32_t aAl0 = smem_to_u32(sAl) + aoff;
    uint32_t aAl1 = aAl0 + 16 * ROWB;
    uint32_t boff = (uint32_t)(n0 + (lane & 7) + ((lane & 16) >> 1)) * ROWB + ((lane & 8) ? 16 : 0);
    uint32_t bBh = smem_to_u32(sBh) + boff;
    uint32_t bBl = smem_to_u32(sBl) + boff;

    float acc[2][NTILES][4];
#pragma unroll
    for (int mm = 0; mm < 2; mm++)
#pragma unroll
        for (int n = 0; n < NTILES; n++)
#pragma unroll
            for (int q = 0; q < 4; q++) acc[mm][n][q] = 0.0f;

#pragma unroll
    for (int ks = 0; ks < 8; ks++) {
        uint32_t kb = ks * 32;
        uint32_t ah[2][4], al[2][4];
        ldsm4(ah[0], aAh0 + kb);
        ldsm4(ah[1], aAh1 + kb);
        ldsm4(al[0], aAl0 + kb);
        ldsm4(al[1], aAl1 + kb);
        uint32_t bh[NPAIR][4], bl[NPAIR][4];
#pragma unroll
        for (int p = 0; p < NPAIR; p++) {
            ldsm4(bh[p], bBh + p * 16 * ROWB + kb);
            ldsm4(bl[p], bBl + p * 16 * ROWB + kb);
        }
#pragma unroll
        for (int mm = 0; mm < 2; mm++)
#pragma unroll
            for (int p = 0; p < NPAIR; p++) {
                mma16816(acc[mm][2 * p + 0], ah[mm], &bh[p][0]);
                mma16816(acc[mm][2 * p + 1], ah[mm], &bh[p][2]);
                mma16816(acc[mm][2 * p + 0], ah[mm], &bl[p][0]);
                mma16816(acc[mm][2 * p + 1], ah[mm], &bl[p][2]);
                mma16816(acc[mm][2 * p + 0], al[mm], &bh[p][0]);
                mma16816(acc[mm][2 * p + 1], al[mm], &bh[p][2]);
            }
    }

#pragma unroll
    for (int mm = 0; mm < 2; mm++) {
        int rbase = block * 128 + r0 + mm * 16 + (lane >> 2);
#pragma unroll
        for (int n = 0; n < NTILES; n++) {
            int col = n0 + n * 8 + (lane & 3) * 2;
            if (col >= NOUT) continue;
            float c0 = acc[mm][n][0], c1 = acc[mm][n][1];
            float c2 = acc[mm][n][2], c3 = acc[mm][n][3];
            if (HOUT) {
                __half* Ch = (__half*)Cv;
                if (rbase < M)
                    *(__half2*)(Ch + (size_t)rbase * NOUT + col) = __floats2half2_rn(c0, c1);
                if (rbase + 8 < M)
                    *(__half2*)(Ch + (size_t)(rbase + 8) * NOUT + col) = __floats2half2_rn(c2, c3);
            } else {
                float* C = (float*)Cv;
                if (bias) {
                    float bx = bias[col], by = bias[col + 1];
                    c0 += bx;
                    c1 += by;
                    c2 += bx;
                    c3 += by;
                }
                if (rbase < M) *(float2*)(C + (size_t)rbase * NOUT + col) = make_float2(c0, c1);
                if (rbase + 8 < M)
                    *(float2*)(C + (size_t)(rbase + 8) * NOUT + col) = make_float2(c2, c3);
            }
        }
    }
}

// ---------------------------------------------------------------------------
// Launcher
// ---------------------------------------------------------------------------
extern "C" void kernel_launch(void* const* d_in, const int* in_sizes, int n_in,
                              void* d_out, int out_size) {
    const float* x   = (const float*)d_in[0];
    const int*   ei  = (const int*)  d_in[1];
    const float* W1  = (const float*)d_in[2];
    const float* b1  = (const float*)d_in[3];
    const float* Wx  = (const float*)d_in[4];
    const float* bx  = (const float*)d_in[5];
    const float* Wfc = (const float*)d_in[6];
    const float* bfc = (const float*)d_in[7];
    float* out = (float*)d_out;

    const int nn = in_sizes[0] / F_HID;   // 50000
    const int ne = in_sizes[1] / 2;       // 800000

    void *pH, *pH1, *pJK, *pDeg;
    void *pW1H, *pW1L, *pWXH, *pWXL, *pWFH, *pWFL;
    cudaGetSymbolAddress(&pH,   g_H);
    cudaGetSymbolAddress(&pH1,  g_h1);
    cudaGetSymbolAddress(&pJK,  g_jk);
    cudaGetSymbolAddress(&pDeg, g_deg);
    cudaGetSymbolAddress(&pW1H, g_w1h);
    cudaGetSymbolAddress(&pW1L, g_w1l);
    cudaGetSymbolAddress(&pWXH, g_wxh);
    cudaGetSymbolAddress(&pWXL, g_wxl);
    cudaGetSymbolAddress(&pWFH, g_wfh);
    cudaGetSymbolAddress(&pWFL, g_wfl);
    __half* H  = (__half*)pH;
    __half* h1 = (__half*)pH1;
    __half* jk = (__half*)pJK;

    const int ngemm = (nn + 127) / 128;   // 391
    const int ne2   = (ne + 1) / 2;
    const int nfill = nn * ELLW;          // 3.2M

    const int SMEM128 = 4 * 128 * 272;                  // 139264
    const int SMEM64  = 2 * 128 * 272 + 2 * 64 * 272;   // 104448
    cudaFuncSetAttribute((const void*)k_gemm<128, 0, true>,
                         cudaFuncAttributeMaxDynamicSharedMemorySize, SMEM128);
    cudaFuncSetAttribute((const void*)k_gemm<128, 1, true>,
                         cudaFuncAttributeMaxDynamicSharedMemorySize, SMEM128);
    cudaFuncSetAttribute((const void*)k_gemm<64, 1, false>,
                         cudaFuncAttributeMaxDynamicSharedMemorySize, SMEM64);

    static cudaStream_t s2 = nullptr;
    static cudaEvent_t ev0 = nullptr, ev1 = nullptr;
    if (!s2) {
        cudaStreamCreateWithFlags(&s2, cudaStreamNonBlocking);
        cudaEventCreateWithFlags(&ev0, cudaEventDisableTiming);
        cudaEventCreateWithFlags(&ev1, cudaEventDisableTiming);
    }

    // zero degree cursors
    cudaMemsetAsync(pDeg, 0, (size_t)nn * sizeof(int), 0);

    // ---- fork: weight splits + GEMM1 on s2, concurrent with ELL build ----
    cudaEventRecord(ev0, 0);
    cudaStreamWaitEvent(s2, ev0, 0);
    k_wsplit_all<<<160, 256, 0, s2>>>(W1, Wx, Wfc);
    k_gemm<128, 0, true><<<ngemm, 256, SMEM128, s2>>>(
        nn, x, (const __nv_bfloat16*)pW1H, (const __nv_bfloat16*)pW1L, nullptr, F_HID, H);
    cudaEventRecord(ev1, s2);

    // ---- single-pass ELL adjacency build + record packing ----
    k_scatter<<<(ne2 + 255) / 256, 256>>>(ei, ne);
    k_dinv<<<(nn + 255) / 256, 256>>>(nn);
    k_fill<<<(nfill + 255) / 256, 256>>>(nn);

    // ---- join + serial chain ----
    cudaStreamWaitEvent(0, ev1, 0);

    k_agg<<<(nn + 7) / 8, 256>>>(H, b1, nullptr, h1, nn);
    k_gemm<128, 1, true><<<ngemm, 256, SMEM128>>>(
        nn, h1, (const __nv_bfloat16*)pWXH, (const __nv_bfloat16*)pWXL, nullptr, F_HID, H);
    k_agg<<<(nn + 7) / 8, 256>>>(H, bx, h1, jk, nn);
    k_gemm<64, 1, false><<<ngemm, 256, SMEM64>>>(
        nn, jk, (const __nv_bfloat16*)pWFH, (const __nv_bfloat16*)pWFL, bfc, N_CLS, out);
}

// round 14
// speedup vs baseline: 1.1549x; 1.1549x over previous
#include <cuda_runtime.h>
#include <cuda_bf16.h>
#include <cuda_fp16.h>
#include <cstdint>
#include <cstddef>

#define NN_MAX 50000
#define NE_MAX 800000
#define F_HID  128
#define N_CLS  40
#define NCLS_PAD 64

// ---------------------------------------------------------------------------
// PTX helpers (compute_100-safe: ldmatrix + mma.sync only)
// ---------------------------------------------------------------------------
__device__ __forceinline__ uint32_t smem_to_u32(const void* p) {
    uint32_t a;
    asm("{ .reg .u64 t; cvta.to.shared.u64 t, %1; cvt.u32.u64 %0, t; }" : "=r"(a) : "l"(p));
    return a;
}
__device__ __forceinline__ void ldsm4(uint32_t* r, uint32_t addr) {
    asm volatile("ldmatrix.sync.aligned.m8n8.x4.shared.b16 {%0,%1,%2,%3}, [%4];"
                 : "=r"(r[0]), "=r"(r[1]), "=r"(r[2]), "=r"(r[3]) : "r"(addr));
}
__device__ __forceinline__ void mma16816(float* c, const uint32_t* a, const uint32_t* b) {
    asm volatile(
        "mma.sync.aligned.m16n8k16.row.col.f32.bf16.bf16.f32 "
        "{%0,%1,%2,%3}, {%4,%5,%6,%7}, {%8,%9}, {%0,%1,%2,%3};"
        : "+f"(c[0]), "+f"(c[1]), "+f"(c[2]), "+f"(c[3])
        : "r"(a[0]), "r"(a[1]), "r"(a[2]), "r"(a[3]), "r"(b[0]), "r"(b[1]));
}

// ---------------------------------------------------------------------------
// Scratch
// ---------------------------------------------------------------------------
__device__ __align__(16) __half g_H [(size_t)NN_MAX * F_HID];  // GEMM out (fp16, pre-agg)
__device__ __align__(16) __half g_h1[(size_t)NN_MAX * F_HID];  // layer-1 act (fp16)
__device__ __align__(16) __half g_jk[(size_t)NN_MAX * F_HID];  // JK-max (fp16)
__device__ __align__(16) __nv_bfloat16 g_w1h[F_HID * F_HID];
__device__ __align__(16) __nv_bfloat16 g_w1l[F_HID * F_HID];
__device__ __align__(16) __nv_bfloat16 g_wxh[F_HID * F_HID];
__device__ __align__(16) __nv_bfloat16 g_wxl[F_HID * F_HID];
__device__ __align__(16) __nv_bfloat16 g_wfh[NCLS_PAD * F_HID];
__device__ __align__(16) __nv_bfloat16 g_wfl[NCLS_PAD * F_HID];
__device__ int   g_deg   [NN_MAX + 1];     // last slot doubles as scan semaphore
__device__ float g_dinv  [NN_MAX];
__device__ int   g_rowptr[NN_MAX + 1];
__device__ int   g_cursor[NN_MAX];
__device__ __align__(16) uint2 g_csre[NE_MAX];   // .x = src, .y = dinv[src] bits
__device__ int   g_part  [256];

// ---------------------------------------------------------------------------
// Graph preprocessing (count/scatter: 2 edges/thread for full occupancy)
// ---------------------------------------------------------------------------
__global__ void k_count(const int* __restrict__ ei, int ne) {
    int base = (blockIdx.x * blockDim.x + threadIdx.x) * 2;
    if (base + 1 < ne) {
        int2 d = *(const int2*)(ei + ne + base);
        atomicAdd(&g_deg[d.x], 1);
        atomicAdd(&g_deg[d.y], 1);
    } else {
        for (int k = base; k < ne; k++) atomicAdd(&g_deg[ei[ne + k]], 1);
    }
}

// Fused part+scan+rowptr: all 196 blocks co-resident.
__global__ void __launch_bounds__(256)
k_scan3(int nn, int ne, int* __restrict__ sem, int nblocks) {
    __shared__ int sh[256];
    int t = threadIdx.x, b = blockIdx.x;
    int i = b * 256 + t;
    int v = (i < nn) ? g_deg[i] : 0;
    sh[t] = v;
    __syncthreads();
    for (int off = 1; off < 256; off <<= 1) {
        int y = (t >= off) ? sh[t - off] : 0;
        __syncthreads();
        sh[t] += y;
        __syncthreads();
    }
    int excl = sh[t] - v;
    int total = sh[255];
    __syncthreads();
    if (t == 0) {
        g_part[b] = total;
        __threadfence();
        atomicAdd(sem, 1);
        while (atomicAdd(sem, 0) < nblocks) { __nanosleep(64); }
    }
    __syncthreads();
    sh[t] = (t < b) ? atomicAdd(&g_part[t], 0) : 0;   // coherent read
    __syncthreads();
    for (int off = 128; off > 0; off >>= 1) {
        if (t < off) sh[t] += sh[t + off];
        __syncthreads();
    }
    int p = sh[0] + excl;
    if (i < nn) {
        g_rowptr[i] = p;
        g_cursor[i] = p;
        g_dinv[i] = rsqrtf((float)v + 1.0f);
    }
    if (b == 0 && t == 0) g_rowptr[nn] = ne;
}

// scatter (src, dinv[src] fp32 bits) per edge; 2 edges/thread
__global__ void k_scatter(const int* __restrict__ ei, int ne) {
    int base = (blockIdx.x * blockDim.x + threadIdx.x) * 2;
    if (base + 1 < ne) {
        int2 s = *(const int2*)(ei + base);
        int2 d = *(const int2*)(ei + ne + base);
        int p0 = atomicAdd(&g_cursor[d.x], 1);
        g_csre[p0] = make_uint2((uint32_t)s.x, __float_as_uint(g_dinv[s.x]));
        int p1 = atomicAdd(&g_cursor[d.y], 1);
        g_csre[p1] = make_uint2((uint32_t)s.y, __float_as_uint(g_dinv[s.y]));
    } else {
        for (int k = base; k < ne; k++) {
            int s = ei[k], d = ei[ne + k];
            int p = atomicAdd(&g_cursor[d], 1);
            g_csre[p] = make_uint2((uint32_t)s, __float_as_uint(g_dinv[s]));
        }
    }
}

// ---------------------------------------------------------------------------
// bf16 hi/lo split
// ---------------------------------------------------------------------------
__device__ __forceinline__ void split_bf16(float v, __nv_bfloat16& hi, __nv_bfloat16& lo) {
    hi = __float2bfloat16(v);
    lo = __float2bfloat16(v - __bfloat162float(hi));
}

// All three weight matrices, transposed + split, one launch.
__global__ void k_wsplit_all(const float* __restrict__ W1, const float* __restrict__ Wx,
                             const float* __restrict__ Wfc) {
    int idx = blockIdx.x * 256 + threadIdx.x;
    const int S1 = F_HID * F_HID;          // 16384
    const int S2 = 2 * S1;                 // 32768
    const int S3 = S2 + NCLS_PAD * F_HID;  // 40960
    if (idx < S1) {
        int n = idx / F_HID, k = idx % F_HID;
        __nv_bfloat16 h, l;
        split_bf16(W1[k * F_HID + n], h, l);
        g_w1h[idx] = h;
        g_w1l[idx] = l;
    } else if (idx < S2) {
        int j = idx - S1;
        int n = j / F_HID, k = j % F_HID;
        __nv_bfloat16 h, l;
        split_bf16(Wx[k * F_HID + n], h, l);
        g_wxh[j] = h;
        g_wxl[j] = l;
    } else if (idx < S3) {
        int j = idx - S2;
        int n = j / F_HID, k = j % F_HID;
        float v = (n < N_CLS) ? Wfc[k * N_CLS + n] : 0.0f;
        __nv_bfloat16 h, l;
        split_bf16(v, h, l);
        g_wfh[j] = h;
        g_wfl[j] = l;
    }
}

// ---------------------------------------------------------------------------
// Aggregation: one WARP = one dst node, 32 lanes x 4 fp16 feats, fp32 FFMA.
// 1024-thread blocks (32 warps) -> 2 CTAs/SM: cuts the cross-CTA L1tex-queue
// contention term (oe x MLP_p1) by 4x vs 256-thread blocks, same warps/SM.
// ---------------------------------------------------------------------------
__device__ __forceinline__ void unp4(uint2 p, float& x, float& y, float& z, float& w) {
    float2 f01 = __half22float2(*(__half2*)&p.x);
    float2 f23 = __half22float2(*(__half2*)&p.y);
    x = f01.x; y = f01.y; z = f23.x; w = f23.y;
}
__global__ void __launch_bounds__(1024)
k_agg(const __half* __restrict__ H, const float* __restrict__ bias,
      const __half* __restrict__ m, __half* __restrict__ outp, int nn) {
    int wid = threadIdx.x >> 5;
    int lane = threadIdx.x & 31;
    int v = blockIdx.x * 32 + wid;
    if (v >= nn) return;

    const uint2* H2 = (const uint2*)H;
    float dv = g_dinv[v];
    float ax, ay, az, aw;
    unp4(H2[(size_t)v * 32 + lane], ax, ay, az, aw);
    ax *= dv; ay *= dv; az *= dv; aw *= dv;

    int s = g_rowptr[v];
    int e = g_rowptr[v + 1];
    int i = s;
    for (; i + 4 <= e; i += 4) {
        uint2 e0 = g_csre[i + 0];
        uint2 e1 = g_csre[i + 1];
        uint2 e2 = g_csre[i + 2];
        uint2 e3 = g_csre[i + 3];
        float w0 = __uint_as_float(e0.y), w1 = __uint_as_float(e1.y);
        float w2 = __uint_as_float(e2.y), w3 = __uint_as_float(e3.y);
        uint2 p0 = H2[(size_t)e0.x * 32 + lane];
        uint2 p1 = H2[(size_t)e1.x * 32 + lane];
        uint2 p2 = H2[(size_t)e2.x * 32 + lane];
        uint2 p3 = H2[(size_t)e3.x * 32 + lane];
        float x0, y0, z0, q0, x1, y1, z1, q1, x2, y2, z2, q2, x3, y3, z3, q3;
        unp4(p0, x0, y0, z0, q0);
        unp4(p1, x1, y1, z1, q1);
        unp4(p2, x2, y2, z2, q2);
        unp4(p3, x3, y3, z3, q3);
        ax += x0 * w0 + x1 * w1 + x2 * w2 + x3 * w3;
        ay += y0 * w0 + y1 * w1 + y2 * w2 + y3 * w3;
        az += z0 * w0 + z1 * w1 + z2 * w2 + z3 * w3;
        aw += q0 * w0 + q1 * w1 + q2 * w2 + q3 * w3;
    }
    for (; i < e; i++) {
        uint2 ew = g_csre[i];
        float w = __uint_as_float(ew.y);
        float x0, y0, z0, q0;
        unp4(H2[(size_t)ew.x * 32 + lane], x0, y0, z0, q0);
        ax += x0 * w;
        ay += y0 * w;
        az += z0 * w;
        aw += q0 * w;
    }

    float4 b = ((const float4*)bias)[lane];
    float rx = fmaxf(ax * dv + b.x, 0.0f);
    float ry = fmaxf(ay * dv + b.y, 0.0f);
    float rz = fmaxf(az * dv + b.z, 0.0f);
    float rw = fmaxf(aw * dv + b.w, 0.0f);
    if (m) {
        uint2 pm = ((const uint2*)m)[(size_t)v * 32 + lane];
        float mx, my, mz, mw;
        unp4(pm, mx, my, mz, mw);
        rx = fmaxf(rx, mx);
        ry = fmaxf(ry, my);
        rz = fmaxf(rz, mz);
        rw = fmaxf(rw, mw);
    }

    uint2 po;
    __half2 o01 = __floats2half2_rn(rx, ry);
    __half2 o23 = __floats2half2_rn(rz, rw);
    po.x = *(uint32_t*)&o01;
    po.y = *(uint32_t*)&o23;
    ((uint2*)outp)[(size_t)v * 32 + lane] = po;
}

// ---------------------------------------------------------------------------
// HMMA GEMM: C[M, NOUT] = (Ah+Al)[M,128] @ (Bh+Bl)^T
// B preformed [NT][128] bf16 hi/lo. AMODE: 0 = A fp32, 1 = A fp16 (both split
// into bf16 hi/lo in-kernel; fp16 split is exact). HOUT: fp16 out else fp32+bias.
// ---------------------------------------------------------------------------
template <int NT, int AMODE, bool HOUT>
__global__ void __launch_bounds__(256)
k_gemm(int M, const void* __restrict__ Av,
       const __nv_bfloat16* __restrict__ Bh, const __nv_bfloat16* __restrict__ Bl,
       const float* __restrict__ bias, int NOUT, void* __restrict__ Cv) {
    extern __shared__ __align__(16) char smem[];
    constexpr int ROWB = 272;
    constexpr int ABYTES = 128 * ROWB;
    constexpr int BBYTES = NT * ROWB;
    constexpr int NTILES = NT / 16;
    constexpr int NPAIR  = NT / 32;

    char* sAh = smem;
    char* sAl = smem + ABYTES;
    char* sBh = smem + 2 * ABYTES;
    char* sBl = smem + 2 * ABYTES + BBYTES;

    int tid = threadIdx.x;
    int block = blockIdx.x;

    if (AMODE == 0) {
        const float* Af = (const float*)Av;
#pragma unroll
        for (int it = 0; it < 16; ++it) {
            int idx = tid + it * 256;
            int r = idx >> 5, c4 = idx & 31;
            int grow = block * 128 + r;
            float4 v = make_float4(0.f, 0.f, 0.f, 0.f);
            if (grow < M) v = *(const float4*)(Af + (size_t)grow * 128 + c4 * 4);
            __nv_bfloat16 h0, l0, h1, l1, h2, l2, h3, l3;
            split_bf16(v.x, h0, l0);
            split_bf16(v.y, h1, l1);
            split_bf16(v.z, h2, l2);
            split_bf16(v.w, h3, l3);
            __nv_bfloat162 a01 = {h0, h1}, a23 = {h2, h3}, b01 = {l0, l1}, b23 = {l2, l3};
            uint2 ph, pl;
            ph.x = *(uint32_t*)&a01;
            ph.y = *(uint32_t*)&a23;
            pl.x = *(uint32_t*)&b01;
            pl.y = *(uint32_t*)&b23;
            *(uint2*)(sAh + r * ROWB + c4 * 8) = ph;
            *(uint2*)(sAl + r * ROWB + c4 * 8) = pl;
        }
    } else {
        const __half* Af = (const __half*)Av;
#pragma unroll
        for (int it = 0; it < 8; ++it) {
            int idx = tid + it * 256;            // 16B fp16 chunks (8 halves)
            int r = idx >> 4, c16 = idx & 15;
            int grow = block * 128 + r;
            uint4 v = make_uint4(0, 0, 0, 0);
            if (grow < M) v = *(const uint4*)(Af + (size_t)grow * 128 + c16 * 8);
            const __half2* hp = (const __half2*)&v;
            uint4 vh, vl;
            uint32_t* vhp = (uint32_t*)&vh;
            uint32_t* vlp = (uint32_t*)&vl;
#pragma unroll
            for (int j = 0; j < 4; j++) {
                float2 f = __half22float2(hp[j]);
                __nv_bfloat16 h0, l0, h1, l1;
                split_bf16(f.x, h0, l0);
                split_bf16(f.y, h1, l1);
                __nv_bfloat162 hh = {h0, h1}, ll = {l0, l1};
                vhp[j] = *(uint32_t*)&hh;
                vlp[j] = *(uint32_t*)&ll;
            }
            *(uint4*)(sAh + r * ROWB + c16 * 16) = vh;
            *(uint4*)(sAl + r * ROWB + c16 * 16) = vl;
        }
    }
    for (int idx = tid; idx < NT * 16; idx += 256) {
        int r = idx >> 4, c16 = idx & 15;
        *(uint4*)(sBh + r * ROWB + c16 * 16) = *(const uint4*)(Bh + (size_t)r * 128 + c16 * 8);
        *(uint4*)(sBl + r * ROWB + c16 * 16) = *(const uint4*)(Bl + (size_t)r * 128 + c16 * 8);
    }
    __syncthreads();

    int wid = tid >> 5, lane = tid & 31;
    int wm = wid & 3, wn = wid >> 2;
    int r0 = wm * 32;
    int n0 = wn * (NT / 2);

    uint32_t aoff = (uint32_t)(r0 + (lane & 15)) * ROWB + ((lane >> 4) * 16);
    uint32_t aAh0 = smem_to_u32(sAh) + aoff;
    uint32_t aAh1 = aAh0 + 16 * ROWB;
    uint32_t aAl0 = smem_to_u32(sAl) + aoff;
    uint32_t aAl1 = aAl0 + 16 * ROWB;
    uint32_t boff = (uint32_t)(n0 + (lane & 7) + ((lane & 16) >> 1)) * ROWB + ((lane & 8) ? 16 : 0);
    uint32_t bBh = smem_to_u32(sBh) + boff;
    uint32_t bBl = smem_to_u32(sBl) + boff;

    float acc[2][NTILES][4];
#pragma unroll
    for (int mm = 0; mm < 2; mm++)
#pragma unroll
        for (int n = 0; n < NTILES; n++)
#pragma unroll
            for (int q = 0; q < 4; q++) acc[mm][n][q] = 0.0f;

#pragma unroll
    for (int ks = 0; ks < 8; ks++) {
        uint32_t kb = ks * 32;
        uint32_t ah[2][4], al[2][4];
        ldsm4(ah[0], aAh0 + kb);
        ldsm4(ah[1], aAh1 + kb);
        ldsm4(al[0], aAl0 + kb);
        ldsm4(al[1], aAl1 + kb);
        uint32_t bh[NPAIR][4], bl[NPAIR][4];
#pragma unroll
        for (int p = 0; p < NPAIR; p++) {
            ldsm4(bh[p], bBh + p * 16 * ROWB + kb);
            ldsm4(bl[p], bBl + p * 16 * ROWB + kb);
        }
#pragma unroll
        for (int mm = 0; mm < 2; mm++)
#pragma unroll
            for (int p = 0; p < NPAIR; p++) {
                mma16816(acc[mm][2 * p + 0], ah[mm], &bh[p][0]);
                mma16816(acc[mm][2 * p + 1], ah[mm], &bh[p][2]);
                mma16816(acc[mm][2 * p + 0], ah[mm], &bl[p][0]);
                mma16816(acc[mm][2 * p + 1], ah[mm], &bl[p][2]);
                mma16816(acc[mm][2 * p + 0], al[mm], &bh[p][0]);
                mma16816(acc[mm][2 * p + 1], al[mm], &bh[p][2]);
            }
    }

#pragma unroll
    for (int mm = 0; mm < 2; mm++) {
        int rbase = block * 128 + r0 + mm * 16 + (lane >> 2);
#pragma unroll
        for (int n = 0; n < NTILES; n++) {
            int col = n0 + n * 8 + (lane & 3) * 2;
            if (col >= NOUT) continue;
            float c0 = acc[mm][n][0], c1 = acc[mm][n][1];
            float c2 = acc[mm][n][2], c3 = acc[mm][n][3];
            if (HOUT) {
                __half* Ch = (__half*)Cv;
                if (rbase < M)
                    *(__half2*)(Ch + (size_t)rbase * NOUT + col) = __floats2half2_rn(c0, c1);
                if (rbase + 8 < M)
                    *(__half2*)(Ch + (size_t)(rbase + 8) * NOUT + col) = __floats2half2_rn(c2, c3);
            } else {
                float* C = (float*)Cv;
                if (bias) {
                    float bx = bias[col], by = bias[col + 1];
                    c0 += bx;
                    c1 += by;
                    c2 += bx;
                    c3 += by;
                }
                if (rbase < M) *(float2*)(C + (size_t)rbase * NOUT + col) = make_float2(c0, c1);
                if (rbase + 8 < M)
                    *(float2*)(C + (size_t)(rbase + 8) * NOUT + col) = make_float2(c2, c3);
            }
        }
    }
}

// ---------------------------------------------------------------------------
// Launcher (R12 structure)
// ---------------------------------------------------------------------------
extern "C" void kernel_launch(void* const* d_in, const int* in_sizes, int n_in,
                              void* d_out, int out_size) {
    const float* x   = (const float*)d_in[0];
    const int*   ei  = (const int*)  d_in[1];
    const float* W1  = (const float*)d_in[2];
    const float* b1  = (const float*)d_in[3];
    const float* Wx  = (const float*)d_in[4];
    const float* bx  = (const float*)d_in[5];
    const float* Wfc = (const float*)d_in[6];
    const float* bfc = (const float*)d_in[7];
    float* out = (float*)d_out;

    const int nn = in_sizes[0] / F_HID;   // 50000
    const int ne = in_sizes[1] / 2;       // 800000

    void *pH, *pH1, *pJK, *pDeg;
    void *pW1H, *pW1L, *pWXH, *pWXL, *pWFH, *pWFL;
    cudaGetSymbolAddress(&pH,   g_H);
    cudaGetSymbolAddress(&pH1,  g_h1);
    cudaGetSymbolAddress(&pJK,  g_jk);
    cudaGetSymbolAddress(&pDeg, g_deg);
    cudaGetSymbolAddress(&pW1H, g_w1h);
    cudaGetSymbolAddress(&pW1L, g_w1l);
    cudaGetSymbolAddress(&pWXH, g_wxh);
    cudaGetSymbolAddress(&pWXL, g_wxl);
    cudaGetSymbolAddress(&pWFH, g_wfh);
    cudaGetSymbolAddress(&pWFL, g_wfl);
    __half* H  = (__half*)pH;
    __half* h1 = (__half*)pH1;
    __half* jk = (__half*)pJK;
    int* sem = (int*)pDeg + nn;           // g_deg[nn] doubles as semaphore

    const int nparts = (nn + 255) / 256;  // 196
    const int ngemm  = (nn + 127) / 128;  // 391
    const int ne2    = (ne + 1) / 2;
    const int naggb  = (nn + 31) / 32;    // 1563 blocks of 1024 threads

    const int SMEM128 = 4 * 128 * 272;                  // 139264
    const int SMEM64  = 2 * 128 * 272 + 2 * 64 * 272;   // 104448
    cudaFuncSetAttribute((const void*)k_gemm<128, 0, true>,
                         cudaFuncAttributeMaxDynamicSharedMemorySize, SMEM128);
    cudaFuncSetAttribute((const void*)k_gemm<128, 1, true>,
                         cudaFuncAttributeMaxDynamicSharedMemorySize, SMEM128);
    cudaFuncSetAttribute((const void*)k_gemm<64, 1, false>,
                         cudaFuncAttributeMaxDynamicSharedMemorySize, SMEM64);

    static cudaStream_t s2 = nullptr;
    static cudaEvent_t ev0 = nullptr, ev1 = nullptr;
    if (!s2) {
        cudaStreamCreateWithFlags(&s2, cudaStreamNonBlocking);
        cudaEventCreateWithFlags(&ev0, cudaEventDisableTiming);
        cudaEventCreateWithFlags(&ev1, cudaEventDisableTiming);
    }

    // zero degrees + semaphore in one memset
    cudaMemsetAsync(pDeg, 0, (size_t)(nn + 1) * sizeof(int), 0);

    // ---- fork: weight splits + GEMM1 on s2, concurrent with CSR build ----
    cudaEventRecord(ev0, 0);
    cudaStreamWaitEvent(s2, ev0, 0);
    k_wsplit_all<<<160, 256, 0, s2>>>(W1, Wx, Wfc);
    k_gemm<128, 0, true><<<ngemm, 256, SMEM128, s2>>>(
        nn, x, (const __nv_bfloat16*)pW1H, (const __nv_bfloat16*)pW1L, nullptr, F_HID, H);
    cudaEventRecord(ev1, s2);

    // ---- CSR build ----
    k_count<<<(ne2 + 255) / 256, 256>>>(ei, ne);
    k_scan3<<<nparts, 256>>>(nn, ne, sem, nparts);
    k_scatter<<<(ne2 + 255) / 256, 256>>>(ei, ne);

    // ---- join + serial chain ----
    cudaStreamWaitEvent(0, ev1, 0);

    k_agg<<<naggb, 1024>>>(H, b1, nullptr, h1, nn);
    k_gemm<128, 1, true><<<ngemm, 256, SMEM128>>>(
        nn, h1, (const __nv_bfloat16*)pWXH, (const __nv_bfloat16*)pWXL, nullptr, F_HID, H);
    k_agg<<<naggb, 1024>>>(H, bx, h1, jk, nn);
    k_gemm<64, 1, false><<<ngemm, 256, SMEM64>>>(
        nn, jk, (const __nv_bfloat16*)pWFH, (const __nv_bfloat16*)pWFL, bfc, N_CLS, out);
}